// round 6
// baseline (speedup 1.0000x reference)
#include <cuda_runtime.h>
#include <cuda_bf16.h>
#include <cuda_fp16.h>

// ---------------------------------------------------------------------------
// GAT 3-layer + PairNorm. N=50000 nodes, E=800000 edges (+N self loops).
//   - CSR-by-dst per call: init+hist -> single-kernel decoupled scan -> scatter.
//   - Per layer: tiled FP32 GEMM (f32x2 FMA, pre-duplicated A pairs) with fused
//     PairNorm+ReLU on the A-load and fused attention-coef epilogue, writing
//     fp16 features -> single-pass softmax aggregation (warp-per-node, 8-deep
//     software-pipelined gathers, no float atomics) with fused column-sum.
//   - Layer 3 fuses head-mean + bias, writes d_out directly.
// ---------------------------------------------------------------------------

#define MAXN 50000
#define MAXE 1000000   // E + N with margin

__device__ __align__(16) __half g_xh[MAXN * 128];
__device__ __align__(16) float g_agg[MAXN * 128];
__device__ __align__(16) float g_als[MAXN * 2];
__device__ __align__(16) float g_ald[MAXN * 2];
__device__ __align__(16) float g_scale[MAXN];
__device__ __align__(16) float g_cs[2][128];
__device__ int g_cnt[MAXN + 1];
__device__ int g_off[MAXN + 1];
__device__ int g_cur[MAXN];
__device__ int g_csr[MAXE];
__device__ int g_bsum[256];
__device__ int g_bpre[256];
__device__ int g_sync[4];
__device__ int g_is64;

// ---------------------------------------------------------------------------
// init: zero counters + sync flags, probe edge_index dtype (int64 vs int32).
// ---------------------------------------------------------------------------
__global__ void init_kernel(const void* ei, int* cnt, int* sync, int N) {
    int i = blockIdx.x * blockDim.x + threadIdx.x;
    if (i < N) cnt[i] = 0;
    if (blockIdx.x == 0 && threadIdx.x < 4) sync[threadIdx.x] = 0;
    if (blockIdx.x == gridDim.x - 1 && threadIdx.x < 32) {
        const long long* p = (const long long*)ei;
        long long v = p[threadIdx.x];
        int ok = (v >= 0 && v < (long long)N);
        unsigned b = __ballot_sync(0xffffffffu, ok);
        if (threadIdx.x == 0) g_is64 = (b == 0xffffffffu) ? 1 : 0;
    }
}

__device__ __forceinline__ int edge_val(const void* ei, int idx) {
    if (g_is64) return (int)((const long long*)ei)[idx];
    return ((const int*)ei)[idx];
}

__global__ void hist_kernel(const void* ei, int E, int Etot, int* cnt) {
    int e = blockIdx.x * blockDim.x + threadIdx.x;
    if (e >= Etot) return;
    int dst = (e < E) ? edge_val(ei, E + e) : (e - E);
    atomicAdd(&cnt[dst], 1);
}

// ---------------------------------------------------------------------------
// Single-kernel decoupled scan. All blocks (196 <= 256) are resident, so
// spin-wait is deadlock-free: last-arriving block scans the block sums and
// releases a flag.
// ---------------------------------------------------------------------------
__global__ void scan_fused_kernel(const int* __restrict__ cnt, int* __restrict__ off,
                                  int* __restrict__ cur, int* __restrict__ bsum,
                                  int* __restrict__ bpre, volatile int* sync, int n) {
    __shared__ int sm[256];
    __shared__ int sm2[256];
    __shared__ int sflag;
    int t = threadIdx.x, b = blockIdx.x, nb = gridDim.x;
    int i = b * 256 + t;
    int v = (i < n) ? cnt[i] : 0;
    sm[t] = v;
    __syncthreads();
#pragma unroll
    for (int d = 1; d < 256; d <<= 1) {
        int x = (t >= d) ? sm[t - d] : 0;
        __syncthreads();
        sm[t] += x;
        __syncthreads();
    }
    if (t == 255) {
        bsum[b] = sm[255];
        __threadfence();
        int tk = atomicAdd((int*)&sync[0], 1);
        sflag = (tk == nb - 1);
    }
    __syncthreads();
    if (sflag) {  // last-arriving block: scan block sums
        int bv = (t < nb) ? bsum[t] : 0;
        sm2[t] = bv;
        __syncthreads();
#pragma unroll
        for (int d = 1; d < 256; d <<= 1) {
            int x = (t >= d) ? sm2[t - d] : 0;
            __syncthreads();
            sm2[t] += x;
            __syncthreads();
        }
        if (t < nb) bpre[t] = sm2[t] - bv;
        if (t == nb - 1) off[n] = sm2[t];
        __threadfence();
        if (t == 0) sync[1] = 1;
    }
    if (t == 0) {
        while (sync[1] == 0) __nanosleep(64);
        sflag = bpre[b];
    }
    __syncthreads();
    if (i < n) {
        int o = sflag + sm[t] - v;
        off[i] = o;
        cur[i] = o;
    }
}

__global__ void scatter_kernel(const void* ei, int E, int Etot, int* cur, int* csr) {
    int e = blockIdx.x * blockDim.x + threadIdx.x;
    if (e >= Etot) return;
    int src, dst;
    if (e < E) { src = edge_val(ei, e); dst = edge_val(ei, E + e); }
    else       { src = dst = e - E; }
    int pos = atomicAdd(&cur[dst], 1);
    csr[pos] = src;
}

// ---------------------------------------------------------------------------
// GEMM: C[N x OW](fp16) = act(A[N x 128]) * W[128 x OW], f32x2 packed FMA.
// A tile staged in smem as pre-duplicated {v,v} u64 pairs -> inner loop is
// LDS.64 + FFMA2 only. P-partials overlay the A tile (union) to fit 48KB.
// If PN: act(v) = relu((v - mean[c]) * scale[row]) fused into A-tile load.
// ---------------------------------------------------------------------------
template <int OW, bool PN>
__global__ void __launch_bounds__(256)
gemm_attn_kernel(const float* __restrict__ A,
                 const float* __restrict__ mean_cs, const float* __restrict__ rscale,
                 const float* __restrict__ W,
                 const float* __restrict__ asrc, const float* __restrict__ adst,
                 __half* __restrict__ C,
                 float* __restrict__ als, float* __restrict__ ald,
                 float* __restrict__ cs_zero, int N) {
    constexpr int BK = 32;
    constexpr int BM = 64;
    constexpr int CT = OW / 8;        // threads along cols
    constexpr int RT = 256 / CT;      // threads along rows
    constexpr int RPT = BM / RT;      // rows per thread
    constexpr int SZ_AS2 = BM * BK * 8;        // 16KB
    constexpr int SZ_WS  = BK * OW * 4;
    __shared__ __align__(16) char sraw[SZ_AS2 + SZ_WS + 128 * 4 + BM * 4];
    typedef unsigned long long u64;
    u64 (*As2)[BK]  = (u64(*)[BK])sraw;
    float (*Ws)[OW] = (float(*)[OW])(sraw + SZ_AS2);
    float* Ms = (float*)(sraw + SZ_AS2 + SZ_WS);
    float* Ss = Ms + 128;
    // epilogue partials overlay the A tile (used only after last __syncthreads)
    float (*Ps0)[CT] = (float(*)[CT])(sraw);
    float (*Pd0)[CT] = (float(*)[CT])(sraw + BM * CT * 4);
    float (*Ps1)[CT] = (float(*)[CT])(sraw + 2 * BM * CT * 4);
    float (*Pd1)[CT] = (float(*)[CT])(sraw + 3 * BM * CT * 4);

    int t = threadIdx.x;
    int tx = t % CT, ty = t / CT;
    int row0 = blockIdx.x * BM;

    if (cs_zero && blockIdx.x == 0 && t < 128) cs_zero[t] = 0.f;
    if (PN) {
        if (t < 128) Ms[t] = mean_cs[t] * (1.0f / (float)N);
        if (t >= 128 && t < 128 + BM) {
            int gr = row0 + t - 128;
            Ss[t - 128] = (gr < N) ? rscale[gr] : 0.f;
        }
        __syncthreads();
    }

    u64 acc2[RPT][4];
#pragma unroll
    for (int r = 0; r < RPT; r++)
#pragma unroll
        for (int j = 0; j < 4; j++) acc2[r][j] = 0ULL;

    for (int k0 = 0; k0 < 128; k0 += BK) {
        for (int i = t; i < BM * BK; i += 256) {
            int r = i / BK, c = i % BK;
            int gr = row0 + r;
            float v = (gr < N) ? A[(size_t)gr * 128 + k0 + c] : 0.f;
            if (PN) v = fmaxf((v - Ms[k0 + c]) * Ss[r], 0.f);
            u64 vv;
            asm("mov.b64 %0, {%1, %1};" : "=l"(vv) : "f"(v));
            As2[r][c] = vv;
        }
        for (int i = t; i < BK * OW; i += 256) {
            int r = i / OW, c = i % OW;
            Ws[r][c] = W[(k0 + r) * OW + c];
        }
        __syncthreads();
#pragma unroll
        for (int kk = 0; kk < BK; kk++) {
            u64 wv2[4];
#pragma unroll
            for (int j = 0; j < 4; j++)
                wv2[j] = *(const u64*)&Ws[kk][2 * tx + j * 2 * CT];
#pragma unroll
            for (int r = 0; r < RPT; r++) {
                u64 av2 = As2[ty * RPT + r][kk];
#pragma unroll
                for (int j = 0; j < 4; j++)
                    asm("fma.rn.f32x2 %0, %1, %2, %0;" : "+l"(acc2[r][j]) : "l"(av2), "l"(wv2[j]));
            }
        }
        __syncthreads();
    }

    float2 av[4], bv[4];
#pragma unroll
    for (int j = 0; j < 4; j++) {
        av[j] = ((const float2*)asrc)[tx + j * CT];
        bv[j] = ((const float2*)adst)[tx + j * CT];
    }

#pragma unroll
    for (int r = 0; r < RPT; r++) {
        int row = ty * RPT + r;
        int gr = row0 + row;
        float s0 = 0.f, d0 = 0.f, s1 = 0.f, d1 = 0.f;
        __half2 c2[4];
#pragma unroll
        for (int j = 0; j < 4; j++) {
            float lo, hi;
            asm("mov.b64 {%0, %1}, %2;" : "=f"(lo), "=f"(hi) : "l"(acc2[r][j]));
            c2[j] = __float22half2_rn(make_float2(lo, hi));
            if (j < 2) {
                s0 = fmaf(lo, av[j].x, fmaf(hi, av[j].y, s0));
                d0 = fmaf(lo, bv[j].x, fmaf(hi, bv[j].y, d0));
            } else {
                s1 = fmaf(lo, av[j].x, fmaf(hi, av[j].y, s1));
                d1 = fmaf(lo, bv[j].x, fmaf(hi, bv[j].y, d1));
            }
        }
        Ps0[row][tx] = s0; Pd0[row][tx] = d0;
        Ps1[row][tx] = s1; Pd1[row][tx] = d1;
        if (gr < N) {
#pragma unroll
            for (int j = 0; j < 4; j++)
                ((__half2*)&C[(size_t)gr * OW])[tx + j * CT] = c2[j];
        }
    }
    __syncthreads();
    if (t < BM * 2) {
        int row = t >> 1, h = t & 1;
        int gr = row0 + row;
        if (gr < N) {
            float s = 0.f, d = 0.f;
#pragma unroll
            for (int k = 0; k < CT; k++) {
                s += h ? Ps1[row][k] : Ps0[row][k];
                d += h ? Pd1[row][k] : Pd0[row][k];
            }
            als[gr * 2 + h] = s;
            ald[gr * 2 + h] = d;
        }
    }
}

__device__ __forceinline__ float lrelu(float x) { return fmaxf(x, 0.2f * x); }

// ---------------------------------------------------------------------------
// Single-pass softmax aggregation over fp16 features, 8-deep software
// pipeline on the edge gathers. Warp (or sub-warp) per destination node;
// fused column-sum (smem staging + 128 REDG).
// ---------------------------------------------------------------------------
template <int HD, bool FINAL>
__global__ void __launch_bounds__(256)
aggr_kernel(const __half* __restrict__ xh,
            const float* __restrict__ als, const float* __restrict__ ald,
            const int* __restrict__ off, const int* __restrict__ csr,
            const float* __restrict__ bias,
            float* __restrict__ out, float* __restrict__ cs, int N) {
    constexpr int D = HD / 2;
    constexpr int L = HD / 4;          // lanes per node (32 or 8)
    constexpr int NPW = 32 / L;        // nodes per warp (1 or 4)
    constexpr int CH = 8;              // pipeline depth
    int wib = threadIdx.x >> 5;
    int wid = blockIdx.x * 8 + wib;
    int lane = threadIdx.x & 31;
    int lig = lane % L;
    int nreq = wid * NPW + lane / L;
    bool valid = nreq < N;
    int n = valid ? nreq : (N - 1);

    float2 ad = ((const float2*)ald)[n];
    int st = off[n], en = off[n + 1];

    int head = (lig * 4) / D;
    float s0 = 0.f, s1 = 0.f;
    float4 acc = make_float4(0.f, 0.f, 0.f, 0.f);
    const uint2* x8 = (const uint2*)xh;

    for (int base = st; base < en; base += CH) {
        int m = en - base;   // >= 1
        int sr[CH]; float2 asr[CH]; uint2 ur[CH];
#pragma unroll
        for (int j = 0; j < CH; j++)
            if (j < m) sr[j] = csr[base + j];
#pragma unroll
        for (int j = 0; j < CH; j++)
            if (j < m) {
                asr[j] = ((const float2*)als)[sr[j]];
                ur[j]  = x8[(size_t)sr[j] * L + lig];
            }
#pragma unroll
        for (int j = 0; j < CH; j++)
            if (j < m) {
                float w0 = __expf(lrelu(asr[j].x + ad.x));
                float w1 = __expf(lrelu(asr[j].y + ad.y));
                s0 += w0; s1 += w1;
                float w = head ? w1 : w0;
                float2 f0 = __half22float2(*(__half2*)&ur[j].x);
                float2 f1 = __half22float2(*(__half2*)&ur[j].y);
                acc.x = fmaf(w, f0.x, acc.x);
                acc.y = fmaf(w, f0.y, acc.y);
                acc.z = fmaf(w, f1.x, acc.z);
                acc.w = fmaf(w, f1.y, acc.w);
            }
    }
    float inv = 1.0f / (head ? s1 : s0);
    acc.x *= inv; acc.y *= inv; acc.z *= inv; acc.w *= inv;

    if (FINAL) {
        float ox = __shfl_down_sync(0xffffffffu, acc.x, 4);
        float oy = __shfl_down_sync(0xffffffffu, acc.y, 4);
        float oz = __shfl_down_sync(0xffffffffu, acc.z, 4);
        float ow = __shfl_down_sync(0xffffffffu, acc.w, 4);
        if (valid && lig < 4) {
            float4 r;
            r.x = 0.5f * (acc.x + ox) + bias[lig * 4 + 0];
            r.y = 0.5f * (acc.y + oy) + bias[lig * 4 + 1];
            r.z = 0.5f * (acc.z + oz) + bias[lig * 4 + 2];
            r.w = 0.5f * (acc.w + ow) + bias[lig * 4 + 3];
            ((float4*)out)[(size_t)n * 4 + lig] = r;
        }
    } else {
        if (valid) ((float4*)out)[(size_t)n * L + lig] = acc;
        __shared__ float csm[8][128];
        float4 a = valid ? acc : make_float4(0.f, 0.f, 0.f, 0.f);
        ((float4*)csm[wib])[lig] = a;
        __syncthreads();
        int t = threadIdx.x;
        if (t < 128) {
            float s = 0.f;
#pragma unroll
            for (int w = 0; w < 8; w++) s += csm[w][t];
            atomicAdd(&cs[t], s);
        }
    }
}

// ---------------------------------------------------------------------------
// Per-row PairNorm scale: scale[n] = 1/(eps + ||row - mean||)
// ---------------------------------------------------------------------------
__global__ void pnscale_kernel(const float* __restrict__ in, const float* __restrict__ cs,
                               float* __restrict__ scale, int N) {
    int wid = (blockIdx.x * blockDim.x + threadIdx.x) >> 5;
    int lane = threadIdx.x & 31;
    if (wid >= N) return;
    float invN = 1.0f / (float)N;
    float4 m = ((const float4*)cs)[lane];
    float4 v = ((const float4*)in)[(size_t)wid * 32 + lane];
    v.x -= m.x * invN; v.y -= m.y * invN; v.z -= m.z * invN; v.w -= m.w * invN;
    float n2 = v.x * v.x + v.y * v.y + v.z * v.z + v.w * v.w;
#pragma unroll
    for (int o = 16; o > 0; o >>= 1) n2 += __shfl_xor_sync(0xffffffffu, n2, o);
    if (lane == 0) scale[wid] = 1.0f / (1e-5f + sqrtf(n2));
}

// ---------------------------------------------------------------------------
extern "C" void kernel_launch(void* const* d_in, const int* in_sizes, int n_in,
                              void* d_out, int out_size) {
    const float* x   = (const float*)d_in[0];
    const void*  ei  = d_in[1];
    const float* W1  = (const float*)d_in[2];
    const float* as1 = (const float*)d_in[3];
    const float* ad1 = (const float*)d_in[4];
    const float* W2  = (const float*)d_in[6];
    const float* as2 = (const float*)d_in[7];
    const float* ad2 = (const float*)d_in[8];
    const float* W3  = (const float*)d_in[10];
    const float* as3 = (const float*)d_in[11];
    const float* ad3 = (const float*)d_in[12];
    const float* b3  = (const float*)d_in[13];

    int N = in_sizes[0] / 128;
    int E = in_sizes[1] / 2;
    int Etot = E + N;

    __half* xh;
    float *agg, *als, *ald, *scl, *cs;
    int *cnt, *off, *cur, *csr, *bsum, *bpre, *sync;
    cudaGetSymbolAddress((void**)&xh, g_xh);
    cudaGetSymbolAddress((void**)&agg, g_agg);
    cudaGetSymbolAddress((void**)&als, g_als);
    cudaGetSymbolAddress((void**)&ald, g_ald);
    cudaGetSymbolAddress((void**)&scl, g_scale);
    cudaGetSymbolAddress((void**)&cs, g_cs);
    cudaGetSymbolAddress((void**)&cnt, g_cnt);
    cudaGetSymbolAddress((void**)&off, g_off);
    cudaGetSymbolAddress((void**)&cur, g_cur);
    cudaGetSymbolAddress((void**)&csr, g_csr);
    cudaGetSymbolAddress((void**)&bsum, g_bsum);
    cudaGetSymbolAddress((void**)&bpre, g_bpre);
    cudaGetSymbolAddress((void**)&sync, g_sync);
    float* cs0 = cs;
    float* cs1 = cs + 128;

    const int TB = 256;
    int ewarp_blocks  = (N + 7) / 8;
    int ewarp_blocks4 = (N / 4 + 7) / 8;
    int gemm_blocks   = (N + 63) / 64;
    int nb1 = (N + 255) / 256;   // must stay <= 256 (N=50000 -> 196)

    // ---- CSR build: 4 launches ----
    init_kernel<<<nb1, 256>>>(ei, cnt, sync, N);                                   // 0
    hist_kernel<<<(Etot + TB - 1) / TB, TB>>>(ei, E, Etot, cnt);                   // 1
    scan_fused_kernel<<<nb1, 256>>>(cnt, off, cur, bsum, bpre, sync, N);           // 2
    scatter_kernel<<<(Etot + TB - 1) / TB, TB>>>(ei, E, Etot, cur, csr);           // 3

    // ---- layer 1 ----
    gemm_attn_kernel<128, false><<<gemm_blocks, TB>>>(x, nullptr, nullptr, W1, as1, ad1,
                                                      xh, als, ald, cs0, N);       // 4
    aggr_kernel<128, false><<<ewarp_blocks, TB>>>(xh, als, ald, off, csr, nullptr,
                                                  agg, cs0, N);                    // 5 <- ncu window
    pnscale_kernel<<<ewarp_blocks, TB>>>(agg, cs0, scl, N);                        // 6

    // ---- layer 2 (PairNorm+ReLU fused into A-load) ----
    gemm_attn_kernel<128, true><<<gemm_blocks, TB>>>(agg, cs0, scl, W2, as2, ad2,
                                                     xh, als, ald, cs1, N);        // 7
    aggr_kernel<128, false><<<ewarp_blocks, TB>>>(xh, als, ald, off, csr, nullptr,
                                                  agg, cs1, N);                    // 8
    pnscale_kernel<<<ewarp_blocks, TB>>>(agg, cs1, scl, N);                        // 9

    // ---- layer 3 (writes d_out with head-mean + bias) ----
    gemm_attn_kernel<32, true><<<gemm_blocks, TB>>>(agg, cs1, scl, W3, as3, ad3,
                                                    xh, als, ald, nullptr, N);     // 10
    aggr_kernel<32, true><<<ewarp_blocks4, TB>>>(xh, als, ald, off, csr, b3,
                                                 (float*)d_out, nullptr, N);       // 11
}

// round 8
// speedup vs baseline: 1.1642x; 1.1642x over previous
#include <cuda_runtime.h>
#include <cuda_bf16.h>

// ---------------------------------------------------------------------------
// GAT 3-layer + PairNorm. N=50000 nodes, E=800000 edges (+N self loops).
//   - CSR-by-dst per call: memset + hist -> fused scan+scatter (grid-resident).
//   - Per layer: tiled FP32 GEMM (f32x2 FMA) with fused PairNorm+ReLU A-load
//     and fused attention-coef epilogue -> single-pass softmax aggregation
//     (warp-per-node, no float atomics) with fused column-sum.
//   - Layer 3 fuses head-mean + bias, writes d_out directly.
// ---------------------------------------------------------------------------

#define MAXN 50000
#define MAXE 1000000   // E + N with margin

__device__ __align__(16) float g_xh[MAXN * 128];
__device__ __align__(16) float g_agg[MAXN * 128];
__device__ __align__(16) float g_als[MAXN * 2];
__device__ __align__(16) float g_ald[MAXN * 2];
__device__ __align__(16) float g_scale[MAXN];
__device__ __align__(16) float g_cs[2][128];
__device__ int g_cnt[MAXN + 1];
__device__ int g_off[MAXN + 1];
__device__ int g_cur[MAXN];
__device__ int g_csr[MAXE];
__device__ int g_bsum[256];
__device__ int g_bpre[256];
__device__ int g_sync[4];
__device__ int g_is64;

__device__ __forceinline__ int edge_val(const void* ei, int idx) {
    if (g_is64) return (int)((const long long*)ei)[idx];
    return ((const int*)ei)[idx];
}

__global__ void hist_kernel(const void* ei, int E, int Etot, int* cnt) {
    int e = blockIdx.x * blockDim.x + threadIdx.x;
    if (e >= Etot) return;
    int dst = (e < E) ? edge_val(ei, E + e) : (e - E);
    atomicAdd(&cnt[dst], 1);
}

// ---------------------------------------------------------------------------
// Fused scan + scatter. 196 blocks (all resident: 196 << 148*8, 2.3KB smem,
// <=32 regs) -> flag-based grid barriers are deadlock-free. Phase 1:
// per-block scan; last-arriving block scans block sums; everyone writes
// off/cur. Phase 2: after second barrier, grid-stride scatter into csr.
// sync[] flags are re-zeroed by a captured memset before each replay.
// ---------------------------------------------------------------------------
__global__ void scanscatter_kernel(const int* __restrict__ cnt, int* __restrict__ off,
                                   int* __restrict__ cur, int* __restrict__ bsum,
                                   int* __restrict__ bpre, volatile int* sync, int n,
                                   const void* ei, int E, int Etot, int* __restrict__ csr) {
    __shared__ int sm[256];
    __shared__ int sm2[256];
    __shared__ int sflag;
    int t = threadIdx.x, b = blockIdx.x, nb = gridDim.x;
    int i = b * 256 + t;
    int v = (i < n) ? cnt[i] : 0;
    sm[t] = v;
    __syncthreads();
#pragma unroll
    for (int d = 1; d < 256; d <<= 1) {
        int x = (t >= d) ? sm[t - d] : 0;
        __syncthreads();
        sm[t] += x;
        __syncthreads();
    }
    if (t == 255) {
        bsum[b] = sm[255];
        __threadfence();
        int tk = atomicAdd((int*)&sync[0], 1);
        sflag = (tk == nb - 1);
    }
    __syncthreads();
    if (sflag) {  // last-arriving block scans the block sums
        int bv = (t < nb) ? bsum[t] : 0;
        sm2[t] = bv;
        __syncthreads();
#pragma unroll
        for (int d = 1; d < 256; d <<= 1) {
            int x = (t >= d) ? sm2[t - d] : 0;
            __syncthreads();
            sm2[t] += x;
            __syncthreads();
        }
        if (t < nb) bpre[t] = sm2[t] - bv;
        if (t == nb - 1) off[n] = sm2[t];
        __threadfence();
        if (t == 0) sync[1] = 1;
    }
    if (t == 0) {
        while (sync[1] == 0) __nanosleep(64);
        sflag = bpre[b];
    }
    __syncthreads();
    if (i < n) {
        int o = sflag + sm[t] - v;
        off[i] = o;
        cur[i] = o;
    }
    // barrier 2: all cur[] writes visible before any scatter atomics
    __threadfence();
    __syncthreads();
    if (t == 0) {
        atomicAdd((int*)&sync[2], 1);
        while (sync[2] < nb) __nanosleep(64);
    }
    __syncthreads();
    // grid-stride scatter
    int nthreads = nb * 256;
    for (int e = b * 256 + t; e < Etot; e += nthreads) {
        int src, dst;
        if (e < E) { src = edge_val(ei, e); dst = edge_val(ei, E + e); }
        else       { src = dst = e - E; }
        int pos = atomicAdd(&cur[dst], 1);
        csr[pos] = src;
    }
}

// ---------------------------------------------------------------------------
// GEMM: C[N x OW] = act(A[N x 128]) * W[128 x OW], f32x2 packed FMA.
// If PN: act(v) = relu((v - mean[c]) * scale[row]) fused into A-tile load.
// Thread (tx,ty) owns column PAIRS (2tx, 2tx+1) + j*2*CT, j=0..3 (8 cols).
// Pairs j=0,1 are head 0; j=2,3 head 1. Fused epilogue: als/ald per (row,head).
// Block 0 zeroes cs_zero[0:128) and (if probe) detects edge dtype.
// ---------------------------------------------------------------------------
template <int OW, bool PN>
__global__ void __launch_bounds__(256)
gemm_attn_kernel(const float* __restrict__ A,
                 const float* __restrict__ mean_cs, const float* __restrict__ rscale,
                 const float* __restrict__ W,
                 const float* __restrict__ asrc, const float* __restrict__ adst,
                 float* __restrict__ C,
                 float* __restrict__ als, float* __restrict__ ald,
                 float* __restrict__ cs_zero, const void* ei_probe, int N) {
    constexpr int BK = 32;
    constexpr int BM = 64;
    constexpr int CT = OW / 8;        // threads along cols
    constexpr int RT = 256 / CT;      // threads along rows
    constexpr int RPT = BM / RT;      // rows per thread
    __shared__ float As[BM][BK + 1];
    __shared__ float Ws[BK][OW];
    __shared__ float Ms[128];
    __shared__ float Ss[BM];
    __shared__ float Ps0[BM][CT], Pd0[BM][CT];
    __shared__ float Ps1[BM][CT], Pd1[BM][CT];
    int t = threadIdx.x;
    int tx = t % CT, ty = t / CT;
    int row0 = blockIdx.x * BM;

    if (cs_zero && blockIdx.x == 0 && t < 128) cs_zero[t] = 0.f;
    if (ei_probe && blockIdx.x == 0 && t < 32) {
        // dtype probe: all first-32 int64 views in [0,N) => int64
        const long long* p = (const long long*)ei_probe;
        long long v = p[t];
        int ok = (v >= 0 && v < (long long)N);
        unsigned b = __ballot_sync(0xffffffffu, ok);
        if (t == 0) g_is64 = (b == 0xffffffffu) ? 1 : 0;
    }
    if (PN) {
        if (t < 128) Ms[t] = mean_cs[t] * (1.0f / (float)N);
        if (t >= 128 && t < 128 + BM) {
            int gr = row0 + t - 128;
            Ss[t - 128] = (gr < N) ? rscale[gr] : 0.f;
        }
        __syncthreads();
    }

    typedef unsigned long long u64;
    u64 acc2[RPT][4];
#pragma unroll
    for (int r = 0; r < RPT; r++)
#pragma unroll
        for (int j = 0; j < 4; j++) acc2[r][j] = 0ULL;

    for (int k0 = 0; k0 < 128; k0 += BK) {
        for (int i = t; i < BM * BK; i += 256) {
            int r = i / BK, c = i % BK;
            int gr = row0 + r;
            float v = (gr < N) ? A[(size_t)gr * 128 + k0 + c] : 0.f;
            if (PN) v = fmaxf((v - Ms[k0 + c]) * Ss[r], 0.f);
            As[r][c] = v;
        }
        for (int i = t; i < BK * OW; i += 256) {
            int r = i / OW, c = i % OW;
            Ws[r][c] = W[(k0 + r) * OW + c];
        }
        __syncthreads();
#pragma unroll
        for (int kk = 0; kk < BK; kk++) {
            u64 wv2[4];
#pragma unroll
            for (int j = 0; j < 4; j++)
                wv2[j] = *(const u64*)&Ws[kk][2 * tx + j * 2 * CT];
#pragma unroll
            for (int r = 0; r < RPT; r++) {
                float av = As[ty * RPT + r][kk];
                u64 av2;
                asm("mov.b64 %0, {%1, %1};" : "=l"(av2) : "f"(av));
#pragma unroll
                for (int j = 0; j < 4; j++)
                    asm("fma.rn.f32x2 %0, %1, %2, %0;" : "+l"(acc2[r][j]) : "l"(av2), "l"(wv2[j]));
            }
        }
        __syncthreads();
    }

    float2 av[4], bv[4];
#pragma unroll
    for (int j = 0; j < 4; j++) {
        av[j] = ((const float2*)asrc)[tx + j * CT];
        bv[j] = ((const float2*)adst)[tx + j * CT];
    }

#pragma unroll
    for (int r = 0; r < RPT; r++) {
        int row = ty * RPT + r;
        int gr = row0 + row;
        float s0 = 0.f, d0 = 0.f, s1 = 0.f, d1 = 0.f;
        float2 c2[4];
#pragma unroll
        for (int j = 0; j < 4; j++) {
            float lo, hi;
            asm("mov.b64 {%0, %1}, %2;" : "=f"(lo), "=f"(hi) : "l"(acc2[r][j]));
            c2[j] = make_float2(lo, hi);
            if (j < 2) {
                s0 = fmaf(lo, av[j].x, fmaf(hi, av[j].y, s0));
                d0 = fmaf(lo, bv[j].x, fmaf(hi, bv[j].y, d0));
            } else {
                s1 = fmaf(lo, av[j].x, fmaf(hi, av[j].y, s1));
                d1 = fmaf(lo, bv[j].x, fmaf(hi, bv[j].y, d1));
            }
        }
        Ps0[row][tx] = s0; Pd0[row][tx] = d0;
        Ps1[row][tx] = s1; Pd1[row][tx] = d1;
        if (gr < N) {
#pragma unroll
            for (int j = 0; j < 4; j++)
                ((float2*)&C[(size_t)gr * OW])[tx + j * CT] = c2[j];
        }
    }
    __syncthreads();
    if (t < BM * 2) {
        int row = t >> 1, h = t & 1;
        int gr = row0 + row;
        if (gr < N) {
            float s = 0.f, d = 0.f;
#pragma unroll
            for (int k = 0; k < CT; k++) {
                s += h ? Ps1[row][k] : Ps0[row][k];
                d += h ? Pd1[row][k] : Pd0[row][k];
            }
            als[gr * 2 + h] = s;
            ald[gr * 2 + h] = d;
        }
    }
}

__device__ __forceinline__ float lrelu(float x) { return fmaxf(x, 0.2f * x); }

// ---------------------------------------------------------------------------
// Single-pass softmax aggregation (logits bounded -> no max subtraction).
// Warp (or sub-warp) per destination node; fused column-sum.
// ---------------------------------------------------------------------------
template <int HD, bool FINAL>
__global__ void __launch_bounds__(256)
aggr_kernel(const float* __restrict__ xh,
            const float* __restrict__ als, const float* __restrict__ ald,
            const int* __restrict__ off, const int* __restrict__ csr,
            const float* __restrict__ bias,
            float* __restrict__ out, float* __restrict__ cs, int N) {
    constexpr int D = HD / 2;
    constexpr int L = HD / 4;          // lanes per node (32 or 8)
    constexpr int NPW = 32 / L;        // nodes per warp (1 or 4)
    int wib = threadIdx.x >> 5;
    int wid = blockIdx.x * 8 + wib;
    int lane = threadIdx.x & 31;
    int lig = lane % L;
    int nreq = wid * NPW + lane / L;
    bool valid = nreq < N;
    int n = valid ? nreq : (N - 1);

    float2 ad = ((const float2*)ald)[n];
    int st = off[n], en = off[n + 1];

    int head = (lig * 4) / D;
    float s0 = 0.f, s1 = 0.f;
    float4 acc = make_float4(0.f, 0.f, 0.f, 0.f);
    const float4* x4 = (const float4*)xh;
#pragma unroll 4
    for (int i = st; i < en; i++) {
        int s = csr[i];
        float2 as = ((const float2*)als)[s];
        float w0 = __expf(lrelu(as.x + ad.x));
        float w1 = __expf(lrelu(as.y + ad.y));
        s0 += w0; s1 += w1;
        float w = head ? w1 : w0;
        float4 v = x4[(size_t)s * L + lig];
        acc.x = fmaf(w, v.x, acc.x);
        acc.y = fmaf(w, v.y, acc.y);
        acc.z = fmaf(w, v.z, acc.z);
        acc.w = fmaf(w, v.w, acc.w);
    }
    float inv = 1.0f / (head ? s1 : s0);
    acc.x *= inv; acc.y *= inv; acc.z *= inv; acc.w *= inv;

    if (FINAL) {
        float ox = __shfl_down_sync(0xffffffffu, acc.x, 4);
        float oy = __shfl_down_sync(0xffffffffu, acc.y, 4);
        float oz = __shfl_down_sync(0xffffffffu, acc.z, 4);
        float ow = __shfl_down_sync(0xffffffffu, acc.w, 4);
        if (valid && lig < 4) {
            float4 r;
            r.x = 0.5f * (acc.x + ox) + bias[lig * 4 + 0];
            r.y = 0.5f * (acc.y + oy) + bias[lig * 4 + 1];
            r.z = 0.5f * (acc.z + oz) + bias[lig * 4 + 2];
            r.w = 0.5f * (acc.w + ow) + bias[lig * 4 + 3];
            ((float4*)out)[(size_t)n * 4 + lig] = r;
        }
    } else {
        if (valid) ((float4*)out)[(size_t)n * L + lig] = acc;
        __shared__ float csm[8][128];
        float4 a = valid ? acc : make_float4(0.f, 0.f, 0.f, 0.f);
        ((float4*)csm[wib])[lig] = a;
        __syncthreads();
        int t = threadIdx.x;
        if (t < 128) {
            float s = 0.f;
#pragma unroll
            for (int w = 0; w < 8; w++) s += csm[w][t];
            atomicAdd(&cs[t], s);
        }
    }
}

// ---------------------------------------------------------------------------
// Per-row PairNorm scale: scale[n] = 1/(eps + ||row - mean||)
// ---------------------------------------------------------------------------
__global__ void pnscale_kernel(const float* __restrict__ in, const float* __restrict__ cs,
                               float* __restrict__ scale, int N) {
    int wid = (blockIdx.x * blockDim.x + threadIdx.x) >> 5;
    int lane = threadIdx.x & 31;
    if (wid >= N) return;
    float invN = 1.0f / (float)N;
    float4 m = ((const float4*)cs)[lane];
    float4 v = ((const float4*)in)[(size_t)wid * 32 + lane];
    v.x -= m.x * invN; v.y -= m.y * invN; v.z -= m.z * invN; v.w -= m.w * invN;
    float n2 = v.x * v.x + v.y * v.y + v.z * v.z + v.w * v.w;
#pragma unroll
    for (int o = 16; o > 0; o >>= 1) n2 += __shfl_xor_sync(0xffffffffu, n2, o);
    if (lane == 0) scale[wid] = 1.0f / (1e-5f + sqrtf(n2));
}

// ---------------------------------------------------------------------------
extern "C" void kernel_launch(void* const* d_in, const int* in_sizes, int n_in,
                              void* d_out, int out_size) {
    const float* x   = (const float*)d_in[0];
    const void*  ei  = d_in[1];
    const float* W1  = (const float*)d_in[2];
    const float* as1 = (const float*)d_in[3];
    const float* ad1 = (const float*)d_in[4];
    const float* W2  = (const float*)d_in[6];
    const float* as2 = (const float*)d_in[7];
    const float* ad2 = (const float*)d_in[8];
    const float* W3  = (const float*)d_in[10];
    const float* as3 = (const float*)d_in[11];
    const float* ad3 = (const float*)d_in[12];
    const float* b3  = (const float*)d_in[13];

    int N = in_sizes[0] / 128;
    int E = in_sizes[1] / 2;
    int Etot = E + N;

    float *xh, *agg, *als, *ald, *scl, *cs;
    int *cnt, *off, *cur, *csr, *bsum, *bpre, *sync;
    cudaGetSymbolAddress((void**)&xh, g_xh);
    cudaGetSymbolAddress((void**)&agg, g_agg);
    cudaGetSymbolAddress((void**)&als, g_als);
    cudaGetSymbolAddress((void**)&ald, g_ald);
    cudaGetSymbolAddress((void**)&scl, g_scale);
    cudaGetSymbolAddress((void**)&cs, g_cs);
    cudaGetSymbolAddress((void**)&cnt, g_cnt);
    cudaGetSymbolAddress((void**)&off, g_off);
    cudaGetSymbolAddress((void**)&cur, g_cur);
    cudaGetSymbolAddress((void**)&csr, g_csr);
    cudaGetSymbolAddress((void**)&bsum, g_bsum);
    cudaGetSymbolAddress((void**)&bpre, g_bpre);
    cudaGetSymbolAddress((void**)&sync, g_sync);
    float* cs0 = cs;
    float* cs1 = cs + 128;

    const int TB = 256;
    int ewarp_blocks  = (N + 7) / 8;
    int ewarp_blocks4 = (N / 4 + 7) / 8;
    int gemm_blocks   = (N + 63) / 64;
    int nb1 = (N + 255) / 256;   // 196 <= 256 (residency requirement)

    // memset nodes (captured into the graph): counters + sync flags
    cudaMemsetAsync(cnt, 0, (size_t)N * sizeof(int));
    cudaMemsetAsync(sync, 0, 4 * sizeof(int));

    // ---- launch 0: GEMM layer 1 (embeds edge-dtype probe) ----
    gemm_attn_kernel<128, false><<<gemm_blocks, TB>>>(x, nullptr, nullptr, W1, as1, ad1,
                                                      xh, als, ald, cs0, ei, N);
    // ---- launch 1: histogram ----
    hist_kernel<<<(Etot + TB - 1) / TB, TB>>>(ei, E, Etot, cnt);
    // ---- launch 2: fused scan + scatter ----
    scanscatter_kernel<<<nb1, 256>>>(cnt, off, cur, bsum, bpre, sync, N, ei, E, Etot, csr);
    // ---- launch 3: aggregation layer 1  <- ncu capture window ----
    aggr_kernel<128, false><<<ewarp_blocks, TB>>>(xh, als, ald, off, csr, nullptr, agg, cs0, N);
    // ---- launch 4 ----
    pnscale_kernel<<<ewarp_blocks, TB>>>(agg, cs0, scl, N);

    // ---- layer 2 (PairNorm+ReLU fused into A-load) ----
    gemm_attn_kernel<128, true><<<gemm_blocks, TB>>>(agg, cs0, scl, W2, as2, ad2,
                                                     xh, als, ald, cs1, nullptr, N);
    aggr_kernel<128, false><<<ewarp_blocks, TB>>>(xh, als, ald, off, csr, nullptr, agg, cs1, N);
    pnscale_kernel<<<ewarp_blocks, TB>>>(agg, cs1, scl, N);

    // ---- layer 3 (writes d_out with head-mean + bias) ----
    gemm_attn_kernel<32, true><<<gemm_blocks, TB>>>(agg, cs1, scl, W3, as3, ad3,
                                                    xh, als, ald, nullptr, nullptr, N);
    aggr_kernel<32, true><<<ewarp_blocks4, TB>>>(xh, als, ald, off, csr, b3,
                                                 (float*)d_out, nullptr, N);
}